// round 11
// baseline (speedup 1.0000x reference)
#include <cuda_runtime.h>
#include <cuda_fp16.h>

#define NCH 256

// fp16 NHWC copies of the three feature maps.
// offsets (halves): L1=0, L2=33554432, L3=41943040, total 44040192 (88MB)
__device__ __half g_nhwc[44040192];

// ---------------------------------------------------------------------------
// NCHW fp32 -> NHWC fp16 transpose (exact R7 version: best measured).
// Tile = 64 channels x 32 cells; one 16B store of 8 channels per thread.
__global__ void __launch_bounds__(256)
nchw_to_nhwc_fp16(const float* __restrict__ feat, size_t dst_off, int HW)
{
    __shared__ float tile[64][33];
    int cell0 = blockIdx.x * 32;
    int c0    = blockIdx.y * 64;
    int b     = blockIdx.z;
    int lane = threadIdx.x & 31;
    int wid  = threadIdx.x >> 5;
    const float* src = feat + (size_t)b * NCH * HW;
#pragma unroll
    for (int k = 0; k < 8; k++) {
        int r = wid + k * 8;
        tile[r][lane] = src[(size_t)(c0 + r) * HW + cell0 + lane];
    }
    __syncthreads();
    int cell = threadIdx.x >> 3;
    int c8   = threadIdx.x & 7;
    uint4 u;
    __half2 h;
    h = __floats2half2_rn(tile[c8*8+0][cell], tile[c8*8+1][cell]); u.x = *(unsigned*)&h;
    h = __floats2half2_rn(tile[c8*8+2][cell], tile[c8*8+3][cell]); u.y = *(unsigned*)&h;
    h = __floats2half2_rn(tile[c8*8+4][cell], tile[c8*8+5][cell]); u.z = *(unsigned*)&h;
    h = __floats2half2_rn(tile[c8*8+6][cell], tile[c8*8+7][cell]); u.w = *(unsigned*)&h;
    size_t addr = ((size_t)b * HW + cell0 + cell) * NCH + c0 + c8 * 8;
    reinterpret_cast<uint4*>(g_nhwc + dst_off)[addr >> 3] = u;
}

// ---------------------------------------------------------------------------
// Gather (exact R7 math, 69.1us measured): one warp = one output pixel,
// lanes cover 256 channels (8 fp16 each; one 16B load per tap). 4-tap half2
// chains per sample (HMUL2/HFMA2), HADD2 tree, single fp32 widen per pixel.
// Natural register allocation (48) — NO launch-bounds cap.

#define TAP0(ptr, wh, s0, s1, s2, s3) do {                                   \
    uint4 _v = __ldg(reinterpret_cast<const uint4*>(ptr));                   \
    const __half2* _h = reinterpret_cast<const __half2*>(&_v);               \
    s0 = __hmul2(wh, _h[0]); s1 = __hmul2(wh, _h[1]);                        \
    s2 = __hmul2(wh, _h[2]); s3 = __hmul2(wh, _h[3]);                        \
} while (0)

#define TAPH(ptr, wh, s0, s1, s2, s3) do {                                   \
    uint4 _v = __ldg(reinterpret_cast<const uint4*>(ptr));                   \
    const __half2* _h = reinterpret_cast<const __half2*>(&_v);               \
    s0 = __hfma2(wh, _h[0], s0); s1 = __hfma2(wh, _h[1], s1);                \
    s2 = __hfma2(wh, _h[2], s2); s3 = __hfma2(wh, _h[3], s3);                \
} while (0)

template <int P, int H, int W>
__device__ __forceinline__ void gather_level(
    const float* __restrict__ rois, float* __restrict__ out_lvl,
    size_t lvl_off, float scale, int pxbase, int npx, float* __restrict__ sacc)
{
    constexpr int pixels = P * P;
    int tid  = threadIdx.x;
    int wid  = tid >> 5;
    int lane = tid & 31;

    for (int j = 0; j < 4; j++) {
        int pxl = j * 8 + wid;
        int gpx = pxbase + pxl;
        float accf[8] = {0.f,0.f,0.f,0.f,0.f,0.f,0.f,0.f};
        if (gpx < npx) {
            int n  = gpx / pixels;
            int p  = gpx - n * pixels;
            int ph = p / P;
            int pw = p - ph * P;
            const float* r = rois + n * 5;
            int   bi = (int)r[0];
            float x1 = fmaf(r[1], scale, -0.5f);
            float y1 = fmaf(r[2], scale, -0.5f);
            float bw = (fmaf(r[3], scale, -0.5f) - x1) * (1.0f / (float)P);
            float bh = (fmaf(r[4], scale, -0.5f) - y1) * (1.0f / (float)P);
            const __half* img = g_nhwc + lvl_off
                              + (size_t)bi * ((size_t)H * W) * NCH + lane * 8;

            __half2 c0[4], c1[4], c2[4], c3[4];
#pragma unroll
            for (int iy = 0; iy < 2; iy++) {
#pragma unroll
                for (int ix = 0; ix < 2; ix++) {
                    float yy = fmaf((float)ph + 0.25f + 0.5f * iy, bh, y1);
                    float xx = fmaf((float)pw + 0.25f + 0.5f * ix, bw, x1);
                    bool valid = (yy > -1.f) && (yy < (float)H) &&
                                 (xx > -1.f) && (xx < (float)W);
                    float yc = fminf(fmaxf(yy, 0.f), (float)(H - 1));
                    float xc = fminf(fmaxf(xx, 0.f), (float)(W - 1));
                    int y0 = (int)yc;
                    int x0 = (int)xc;
                    float wy1 = (y0 >= H - 1) ? 1.f : yc - (float)y0;
                    float wx1 = (x0 >= W - 1) ? 1.f : xc - (float)x0;
                    int ya = min(y0, H - 2);
                    int xa = min(x0, W - 2);
                    float ws  = valid ? 0.25f : 0.f;
                    __half2 w00 = __float2half2_rn((1.f - wy1) * (1.f - wx1) * ws);
                    __half2 w01 = __float2half2_rn((1.f - wy1) * wx1 * ws);
                    __half2 w10 = __float2half2_rn(wy1 * (1.f - wx1) * ws);
                    __half2 w11 = __float2half2_rn(wy1 * wx1 * ws);
                    const __half* f = img + (size_t)(ya * W + xa) * NCH;
                    __half2 *s0, *s1, *s2, *s3;
                    int s = iy * 2 + ix;
                    if (s == 0)      { s0=&c0[0]; s1=&c0[1]; s2=&c0[2]; s3=&c0[3]; }
                    else if (s == 1) { s0=&c1[0]; s1=&c1[1]; s2=&c1[2]; s3=&c1[3]; }
                    else if (s == 2) { s0=&c2[0]; s1=&c2[1]; s2=&c2[2]; s3=&c2[3]; }
                    else             { s0=&c3[0]; s1=&c3[1]; s2=&c3[2]; s3=&c3[3]; }
                    TAP0(f,                       w00, *s0, *s1, *s2, *s3);
                    TAPH(f + NCH,                 w01, *s0, *s1, *s2, *s3);
                    TAPH(f + (size_t)W * NCH,     w10, *s0, *s1, *s2, *s3);
                    TAPH(f + (size_t)(W+1) * NCH, w11, *s0, *s1, *s2, *s3);
                }
            }
#pragma unroll
            for (int rgi = 0; rgi < 4; rgi++) {
                __half2 u = __hadd2(c0[rgi], c1[rgi]);
                __half2 v = __hadd2(c2[rgi], c3[rgi]);
                __half2 t = __hadd2(u, v);
                accf[rgi * 2 + 0] = __low2float(t);
                accf[rgi * 2 + 1] = __high2float(t);
            }
        }
        int col = pxl ^ lane;
#pragma unroll
        for (int i = 0; i < 8; i++)
            sacc[(lane * 8 + i) * 32 + col] = accf[i];
    }
    __syncthreads();

    int pxlane = tid & 31;
    int gpx = pxbase + pxlane;
    if (gpx < npx) {
        int n = gpx / pixels;
        int p = gpx - n * pixels;
        float* ob = out_lvl + (size_t)n * NCH * pixels + p;
        int c0i = (tid >> 5) * 32;
#pragma unroll
        for (int i = 0; i < 32; i++) {
            int c = c0i + i;
            ob[(size_t)c * pixels] = sacc[c * 32 + (pxlane ^ ((c >> 3) & 31))];
        }
    }
}

// Level-1-only gather (stream A, after T1)
__global__ void __launch_bounds__(256)
roi_gather_l1(const float* __restrict__ rois, float* __restrict__ out, int N)
{
    __shared__ float sacc[NCH * 32];
    gather_level<28, 256, 256>(rois, out, 0ull, 0.25f,
                               blockIdx.x * 32, N * 784, sacc);
}

// Levels 2+3 gather (stream B, after T2/T3)
__global__ void __launch_bounds__(256)
roi_gather_l23(const float* __restrict__ rois, float* __restrict__ out,
               int N, int nb2)
{
    __shared__ float sacc[NCH * 32];
    float* o2 = out + (size_t)N * NCH * 784;
    float* o3 = o2  + (size_t)N * NCH * 196;
    int blk = blockIdx.x;
    if (blk < nb2) {
        gather_level<14, 128, 128>(rois, o2, 33554432ull, 0.125f,
                                   blk * 32, N * 196, sacc);
    } else {
        gather_level<7, 64, 64>(rois, o3, 41943040ull, 0.0625f,
                                (blk - nb2) * 32, N * 49, sacc);
    }
}

// ---------------------------------------------------------------------------
// All real work runs on created NON-BLOCKING streams; the capture (default)
// stream only records the fork event and waits on the join events. This
// avoids legacy-default-stream implicit synchronization linearizing the
// captured graph (suspected cause of R10's zero overlap).
struct RAStreams {
    cudaStream_t sA, sB;
    cudaEvent_t  fork, joinA, joinB;
    RAStreams() {
        cudaStreamCreateWithFlags(&sA, cudaStreamNonBlocking);
        cudaStreamCreateWithFlags(&sB, cudaStreamNonBlocking);
        cudaEventCreateWithFlags(&fork,  cudaEventDisableTiming);
        cudaEventCreateWithFlags(&joinA, cudaEventDisableTiming);
        cudaEventCreateWithFlags(&joinB, cudaEventDisableTiming);
    }
};
static RAStreams g_rs;

extern "C" void kernel_launch(void* const* d_in, const int* in_sizes, int n_in,
                              void* d_out, int out_size)
{
    const float* feat1 = (const float*)d_in[0];  // (2,256,256,256)
    const float* feat2 = (const float*)d_in[1];  // (2,256,128,128)
    const float* feat3 = (const float*)d_in[2];  // (2,256,64,64)
    const float* rois  = (const float*)d_in[3];  // (N,5)
    float* out = (float*)d_out;

    const int N = in_sizes[3] / 5;
    int nb1 = (N * 784 + 31) / 32;
    int nb2 = (N * 196 + 31) / 32;
    int nb3 = (N * 49  + 31) / 32;

    // fork both created streams off the capture (default) stream
    cudaEventRecord(g_rs.fork, 0);
    cudaStreamWaitEvent(g_rs.sA, g_rs.fork, 0);
    cudaStreamWaitEvent(g_rs.sB, g_rs.fork, 0);

    // stream B: small transposes + level-2/3 gather (issued first so it can
    // interleave with T1's long DRAM phase)
    {
        dim3 g2(16384 / 32, 4, 2);
        nchw_to_nhwc_fp16<<<g2, 256, 0, g_rs.sB>>>(feat2, 33554432ull, 16384);
        dim3 g3(4096 / 32, 4, 2);
        nchw_to_nhwc_fp16<<<g3, 256, 0, g_rs.sB>>>(feat3, 41943040ull, 4096);
        roi_gather_l23<<<nb2 + nb3, 256, 0, g_rs.sB>>>(rois, out, N, nb2);
    }

    // stream A: big level-1 transpose, then level-1 gather
    {
        dim3 g1(65536 / 32, 4, 2);
        nchw_to_nhwc_fp16<<<g1, 256, 0, g_rs.sA>>>(feat1, 0ull, 65536);
        roi_gather_l1<<<nb1, 256, 0, g_rs.sA>>>(rois, out, N);
    }

    // join both streams back into the capture stream
    cudaEventRecord(g_rs.joinA, g_rs.sA);
    cudaEventRecord(g_rs.joinB, g_rs.sB);
    cudaStreamWaitEvent(0, g_rs.joinA, 0);
    cudaStreamWaitEvent(0, g_rs.joinB, 0);
}

// round 12
// speedup vs baseline: 1.1044x; 1.1044x over previous
#include <cuda_runtime.h>
#include <cuda_fp16.h>

#define NCH 256

// fp16 NHWC copies of the three feature maps.
// offsets (halves): L1=0, L2=33554432, L3=41943040, total 44040192 (88MB)
__device__ __half g_nhwc[44040192];

// ---------------------------------------------------------------------------
// Fused NCHW fp32 -> NHWC fp16 transpose: all 3 levels in ONE launch.
// Per-tile code identical to the measured-best R7 version (64ch x 32cell,
// one 16B store of 8 channels per thread). Level decoded from blockIdx.x;
// level-1 blocks first so small-level blocks fill the tail waves.
__global__ void __launch_bounds__(256)
nchw_to_nhwc_fused(const float* __restrict__ f1,
                   const float* __restrict__ f2,
                   const float* __restrict__ f3)
{
    __shared__ float tile[64][33];

    int blk = blockIdx.x;
    const float* feat; size_t dst_off; int HW; int t;
    if (blk < 16384)      { feat = f1; dst_off = 0ull;        HW = 65536; t = blk; }
    else if (blk < 20480) { feat = f2; dst_off = 33554432ull; HW = 16384; t = blk - 16384; }
    else                  { feat = f3; dst_off = 41943040ull; HW = 4096;  t = blk - 20480; }

    int nx = HW / 32;                 // cell-tiles per image per channel group
    int cell0 = (t % nx) * 32;
    int rem   = t / nx;
    int c0    = (rem & 3) * 64;
    int b     = rem >> 2;

    int lane = threadIdx.x & 31;
    int wid  = threadIdx.x >> 5;
    const float* src = feat + (size_t)b * NCH * HW;
#pragma unroll
    for (int k = 0; k < 8; k++) {
        int r = wid + k * 8;
        tile[r][lane] = src[(size_t)(c0 + r) * HW + cell0 + lane];
    }
    __syncthreads();
    int cell = threadIdx.x >> 3;
    int c8   = threadIdx.x & 7;
    uint4 u;
    __half2 h;
    h = __floats2half2_rn(tile[c8*8+0][cell], tile[c8*8+1][cell]); u.x = *(unsigned*)&h;
    h = __floats2half2_rn(tile[c8*8+2][cell], tile[c8*8+3][cell]); u.y = *(unsigned*)&h;
    h = __floats2half2_rn(tile[c8*8+4][cell], tile[c8*8+5][cell]); u.z = *(unsigned*)&h;
    h = __floats2half2_rn(tile[c8*8+6][cell], tile[c8*8+7][cell]); u.w = *(unsigned*)&h;
    size_t addr = ((size_t)b * HW + cell0 + cell) * NCH + c0 + c8 * 8;
    reinterpret_cast<uint4*>(g_nhwc + dst_off)[addr >> 3] = u;
}

// ---------------------------------------------------------------------------
// Gather: one warp = one output pixel, lanes cover 256 channels (8 fp16 each;
// one 16B load per tap). R7 tap math (4-tap half2 chains, HADD2 tree) but the
// pixel result stays in half2: stored packed to 16KB smem; fp32 widening
// happens once in the store phase. Natural registers — NO launch-bounds cap.

#define TAP0(ptr, wh, s0, s1, s2, s3) do {                                   \
    uint4 _v = __ldg(reinterpret_cast<const uint4*>(ptr));                   \
    const __half2* _h = reinterpret_cast<const __half2*>(&_v);               \
    s0 = __hmul2(wh, _h[0]); s1 = __hmul2(wh, _h[1]);                        \
    s2 = __hmul2(wh, _h[2]); s3 = __hmul2(wh, _h[3]);                        \
} while (0)

#define TAPH(ptr, wh, s0, s1, s2, s3) do {                                   \
    uint4 _v = __ldg(reinterpret_cast<const uint4*>(ptr));                   \
    const __half2* _h = reinterpret_cast<const __half2*>(&_v);               \
    s0 = __hfma2(wh, _h[0], s0); s1 = __hfma2(wh, _h[1], s1);                \
    s2 = __hfma2(wh, _h[2], s2); s3 = __hfma2(wh, _h[3], s3);                \
} while (0)

template <int P, int H, int W>
__device__ __forceinline__ void gather_level(
    const float* __restrict__ rois, float* __restrict__ out_lvl,
    size_t lvl_off, float scale, int pxbase, int npx,
    unsigned* __restrict__ sacc)       // [128 pairs][32 px], half2-packed
{
    constexpr int pixels = P * P;
    int tid  = threadIdx.x;
    int wid  = tid >> 5;
    int lane = tid & 31;

    for (int j = 0; j < 4; j++) {
        int pxl = j * 8 + wid;
        int gpx = pxbase + pxl;
        __half2 res[4] = {__float2half2_rn(0.f), __float2half2_rn(0.f),
                          __float2half2_rn(0.f), __float2half2_rn(0.f)};
        if (gpx < npx) {
            int n  = gpx / pixels;
            int p  = gpx - n * pixels;
            int ph = p / P;
            int pw = p - ph * P;
            const float* r = rois + n * 5;
            int   bi = (int)r[0];
            float x1 = fmaf(r[1], scale, -0.5f);
            float y1 = fmaf(r[2], scale, -0.5f);
            float bw = (fmaf(r[3], scale, -0.5f) - x1) * (1.0f / (float)P);
            float bh = (fmaf(r[4], scale, -0.5f) - y1) * (1.0f / (float)P);
            const __half* img = g_nhwc + lvl_off
                              + (size_t)bi * ((size_t)H * W) * NCH + lane * 8;

            __half2 c0[4], c1[4], c2[4], c3[4];
#pragma unroll
            for (int iy = 0; iy < 2; iy++) {
#pragma unroll
                for (int ix = 0; ix < 2; ix++) {
                    float yy = fmaf((float)ph + 0.25f + 0.5f * iy, bh, y1);
                    float xx = fmaf((float)pw + 0.25f + 0.5f * ix, bw, x1);
                    bool valid = (yy > -1.f) && (yy < (float)H) &&
                                 (xx > -1.f) && (xx < (float)W);
                    float yc = fminf(fmaxf(yy, 0.f), (float)(H - 1));
                    float xc = fminf(fmaxf(xx, 0.f), (float)(W - 1));
                    int y0 = (int)yc;
                    int x0 = (int)xc;
                    float wy1 = (y0 >= H - 1) ? 1.f : yc - (float)y0;
                    float wx1 = (x0 >= W - 1) ? 1.f : xc - (float)x0;
                    int ya = min(y0, H - 2);
                    int xa = min(x0, W - 2);
                    float ws  = valid ? 0.25f : 0.f;
                    __half2 w00 = __float2half2_rn((1.f - wy1) * (1.f - wx1) * ws);
                    __half2 w01 = __float2half2_rn((1.f - wy1) * wx1 * ws);
                    __half2 w10 = __float2half2_rn(wy1 * (1.f - wx1) * ws);
                    __half2 w11 = __float2half2_rn(wy1 * wx1 * ws);
                    const __half* f = img + (size_t)(ya * W + xa) * NCH;
                    __half2 *s0, *s1, *s2, *s3;
                    int s = iy * 2 + ix;
                    if (s == 0)      { s0=&c0[0]; s1=&c0[1]; s2=&c0[2]; s3=&c0[3]; }
                    else if (s == 1) { s0=&c1[0]; s1=&c1[1]; s2=&c1[2]; s3=&c1[3]; }
                    else if (s == 2) { s0=&c2[0]; s1=&c2[1]; s2=&c2[2]; s3=&c2[3]; }
                    else             { s0=&c3[0]; s1=&c3[1]; s2=&c3[2]; s3=&c3[3]; }
                    TAP0(f,                       w00, *s0, *s1, *s2, *s3);
                    TAPH(f + NCH,                 w01, *s0, *s1, *s2, *s3);
                    TAPH(f + (size_t)W * NCH,     w10, *s0, *s1, *s2, *s3);
                    TAPH(f + (size_t)(W+1) * NCH, w11, *s0, *s1, *s2, *s3);
                }
            }
#pragma unroll
            for (int rgi = 0; rgi < 4; rgi++) {
                __half2 u = __hadd2(c0[rgi], c1[rgi]);
                __half2 v = __hadd2(c2[rgi], c3[rgi]);
                res[rgi] = __hadd2(u, v);
            }
        }
        // pair row = 4*lane+rgi, col = pxl ^ lane  -> bank = pxl^lane: CF
        int col = pxl ^ lane;
#pragma unroll
        for (int rgi = 0; rgi < 4; rgi++)
            sacc[(4 * lane + rgi) * 32 + col] = *(unsigned*)&res[rgi];
    }
    __syncthreads();

    // store phase: lanes along pixels; each thread: 16 pairs -> 32 rows
    int pxlane = tid & 31;
    int gpx = pxbase + pxlane;
    if (gpx < npx) {
        int n = gpx / pixels;
        int p = gpx - n * pixels;
        float* ob = out_lvl + (size_t)n * NCH * pixels + p;
        int pp0 = (tid >> 5) * 16;
#pragma unroll
        for (int i = 0; i < 16; i++) {
            int pp = pp0 + i;
            unsigned u = sacc[pp * 32 + (pxlane ^ (pp >> 2))];
            __half2 h = *(__half2*)&u;
            int c = 2 * pp;
            ob[(size_t)c       * pixels] = __low2float(h);
            ob[(size_t)(c + 1) * pixels] = __high2float(h);
        }
    }
}

__global__ void __launch_bounds__(256)
roi_gather_kernel(const float* __restrict__ rois, float* __restrict__ out,
                  int N, int nb1, int nb2)
{
    __shared__ unsigned sacc[128 * 32];   // 16KB
    int blk = blockIdx.x;
    if (blk < nb1) {
        gather_level<28, 256, 256>(rois, out, 0ull, 0.25f,
                                   blk * 32, N * 784, sacc);
    } else if (blk < nb1 + nb2) {
        float* o2 = out + (size_t)N * NCH * 784;
        gather_level<14, 128, 128>(rois, o2, 33554432ull, 0.125f,
                                   (blk - nb1) * 32, N * 196, sacc);
    } else {
        float* o3 = out + (size_t)N * NCH * (784 + 196);
        gather_level<7, 64, 64>(rois, o3, 41943040ull, 0.0625f,
                                (blk - nb1 - nb2) * 32, N * 49, sacc);
    }
}

// ---------------------------------------------------------------------------
extern "C" void kernel_launch(void* const* d_in, const int* in_sizes, int n_in,
                              void* d_out, int out_size)
{
    const float* feat1 = (const float*)d_in[0];  // (2,256,256,256)
    const float* feat2 = (const float*)d_in[1];  // (2,256,128,128)
    const float* feat3 = (const float*)d_in[2];  // (2,256,64,64)
    const float* rois  = (const float*)d_in[3];  // (N,5)
    float* out = (float*)d_out;

    const int N = in_sizes[3] / 5;

    // 1) fused transpose: 16384 (L1) + 4096 (L2) + 1024 (L3) blocks
    nchw_to_nhwc_fused<<<21504, 256>>>(feat1, feat2, feat3);

    // 2) fused gather over all three levels
    int nb1 = (N * 784 + 31) / 32;
    int nb2 = (N * 196 + 31) / 32;
    int nb3 = (N * 49  + 31) / 32;
    roi_gather_kernel<<<nb1 + nb2 + nb3, 256>>>(rois, out, N, nb1, nb2);
}